// round 15
// baseline (speedup 1.0000x reference)
#include <cuda_runtime.h>
#include <cuda_fp16.h>

#define NROWS 4096
#define DIM 256
#define EXPSC 14.4269504088896340736f  /* 10 * log2(e) */
#define SQRT_EXPSC 3.7982825381f       /* sqrt(EXPSC) */

// persistent device scratch (no allocations allowed)
// z vectors are L2-normalized, scaled by SQRT_EXPSC, quantized to e4m3.
// Dot of two stored vectors = EXPSC * cosine_sim (exp2-ready).
__device__ unsigned char g_z1[NROWS * DIM];
__device__ unsigned char g_z2[NROWS * DIM];
// 0: rowsum(exp sim12, diag zeroed), 1: colsum(exp sim12, diag zeroed),
// 2: rowsum(exp sim11 masked), 3: rowsum(exp sim22 masked)
__device__ float g_rowsum[4][NROWS];
__device__ float g_diag[NROWS];        // exact fp32 cosine(x1_i, x2_i)

__device__ __forceinline__ float fast_ex2(float x) {
    float y;
    asm("ex2.approx.f32 %0, %1;" : "=f"(y) : "f"(x));
    return y;
}
__device__ __forceinline__ unsigned ex2h2(unsigned x) {
    unsigned y;
    asm("ex2.approx.f16x2 %0, %1;" : "=r"(y) : "r"(x));
    return y;
}
__device__ __forceinline__ unsigned hadd2u(unsigned a, unsigned b) {
    unsigned d;
    asm("add.rn.f16x2 %0, %1, %2;" : "=r"(d) : "r"(a), "r"(b));
    return d;
}

// ---------------------------------------------------------------------------
// Kernel 1: per row i, load x1_i and x2_i once: norms, EXACT fp32 cross dot
// -> g_diag; L2-normalize * SQRT_EXPSC -> e4m3 z1/z2. Zeroes g_rowsum.
// One warp per row pair.
// ---------------------------------------------------------------------------
__global__ void normalize_kernel(const float* __restrict__ x1,
                                 const float* __restrict__ x2) {
    int gt = blockIdx.x * blockDim.x + threadIdx.x;
    if (gt < 4 * NROWS) (&g_rowsum[0][0])[gt] = 0.0f;

    int w = gt >> 5;                 // row index 0..NROWS-1
    int lane = threadIdx.x & 31;

    const float4* p1 = (const float4*)(x1 + w * DIM);
    const float4* p2 = (const float4*)(x2 + w * DIM);
    float4 a0 = p1[lane], a1 = p1[lane + 32];
    float4 b0 = p2[lane], b1 = p2[lane + 32];

    float s1 = a0.x*a0.x + a0.y*a0.y + a0.z*a0.z + a0.w*a0.w
             + a1.x*a1.x + a1.y*a1.y + a1.z*a1.z + a1.w*a1.w;
    float s2 = b0.x*b0.x + b0.y*b0.y + b0.z*b0.z + b0.w*b0.w
             + b1.x*b1.x + b1.y*b1.y + b1.z*b1.z + b1.w*b1.w;
    float dd = a0.x*b0.x + a0.y*b0.y + a0.z*b0.z + a0.w*b0.w
             + a1.x*b1.x + a1.y*b1.y + a1.z*b1.z + a1.w*b1.w;
#pragma unroll
    for (int o = 16; o; o >>= 1) {
        s1 += __shfl_xor_sync(0xffffffffu, s1, o);
        s2 += __shfl_xor_sync(0xffffffffu, s2, o);
        dd += __shfl_xor_sync(0xffffffffu, dd, o);
    }
    float n1 = fmaxf(sqrtf(s1), 1e-8f);
    float n2 = fmaxf(sqrtf(s2), 1e-8f);
    float sc1 = SQRT_EXPSC / n1;
    float sc2 = SQRT_EXPSC / n2;

    unsigned short q0, q1, q2, q3;
    asm("cvt.rn.satfinite.e4m3x2.f32 %0, %1, %2;" : "=h"(q0) : "f"(a0.y * sc1), "f"(a0.x * sc1));
    asm("cvt.rn.satfinite.e4m3x2.f32 %0, %1, %2;" : "=h"(q1) : "f"(a0.w * sc1), "f"(a0.z * sc1));
    asm("cvt.rn.satfinite.e4m3x2.f32 %0, %1, %2;" : "=h"(q2) : "f"(a1.y * sc1), "f"(a1.x * sc1));
    asm("cvt.rn.satfinite.e4m3x2.f32 %0, %1, %2;" : "=h"(q3) : "f"(a1.w * sc1), "f"(a1.z * sc1));
    unsigned w0, w1;
    asm("mov.b32 %0, {%1, %2};" : "=r"(w0) : "h"(q0), "h"(q1));
    asm("mov.b32 %0, {%1, %2};" : "=r"(w1) : "h"(q2), "h"(q3));
    *(unsigned*)(g_z1 + w * DIM + 4 * lane)       = w0;
    *(unsigned*)(g_z1 + w * DIM + 128 + 4 * lane) = w1;

    asm("cvt.rn.satfinite.e4m3x2.f32 %0, %1, %2;" : "=h"(q0) : "f"(b0.y * sc2), "f"(b0.x * sc2));
    asm("cvt.rn.satfinite.e4m3x2.f32 %0, %1, %2;" : "=h"(q1) : "f"(b0.w * sc2), "f"(b0.z * sc2));
    asm("cvt.rn.satfinite.e4m3x2.f32 %0, %1, %2;" : "=h"(q2) : "f"(b1.y * sc2), "f"(b1.x * sc2));
    asm("cvt.rn.satfinite.e4m3x2.f32 %0, %1, %2;" : "=h"(q3) : "f"(b1.w * sc2), "f"(b1.z * sc2));
    asm("mov.b32 %0, {%1, %2};" : "=r"(w0) : "h"(q0), "h"(q1));
    asm("mov.b32 %0, {%1, %2};" : "=r"(w1) : "h"(q2), "h"(q3));
    *(unsigned*)(g_z2 + w * DIM + 4 * lane)       = w0;
    *(unsigned*)(g_z2 + w * DIM + 128 + 4 * lane) = w1;

    if (lane == 0) g_diag[w] = dd / (n1 * n2);
}

// ---------------------------------------------------------------------------
// Kernel 2: fused tile-GEMM + exp row/col-reduce. 148 CTAs, 2 warp-groups,
// e4m3 inputs + FP16 ACCUMULATE via mma.m16n8k32 (K=32/instr, full rate:
// half the MMA and half the ldsm of the fp16 path). 64x64 warp tiles,
// group tile 128x128xK256. A = 32KB fp8, B = 32KB/tile, double-buffered per
// group, single outstanding cp group, ONE group barrier per tile.
// Diagonal zeroed (exact); loss kernel re-adds exp(10*diag12) from g_diag.
//   CTA 0..73   : sim12 (z1 x z2^T), 1024 tiles.  row->rs[0], col->rs[1].
//   CTA 74..110 : sim11 upper-tri (528 tiles, pair-ordered stripes).
//   CTA 111..147: sim22 upper-tri.   row->target; col->target by symmetry
//                 (diagonal tiles: rowsum only — full tile computed).
// ---------------------------------------------------------------------------
#define SWZ8(r, c) (((r) << 8) | ((((c) ^ ((r) & 7)) & 15) << 4))   /* 256B rows */
#define SMEM_A 0
#define SMEM_B(grp, buf) (32768 + ((grp) * 2 + (buf)) * 32768)
#define SMEM_TOTAL 163840

__device__ __forceinline__ void cp16(unsigned d, const void* s) {
    asm volatile("cp.async.cg.shared.global [%0], [%1], 16;" :: "r"(d), "l"(s));
}
__device__ __forceinline__ void cp_commit() {
    asm volatile("cp.async.commit_group;");
}
template <int n>
__device__ __forceinline__ void cp_wait() {
    asm volatile("cp.async.wait_group %0;" :: "n"(n));
}
__device__ __forceinline__ void ldsm4(unsigned (&r)[4], unsigned addr) {
    asm volatile("ldmatrix.sync.aligned.m8n8.x4.shared.b16 {%0,%1,%2,%3}, [%4];"
                 : "=r"(r[0]), "=r"(r[1]), "=r"(r[2]), "=r"(r[3]) : "r"(addr));
}
__device__ __forceinline__ void mma_fp8h(unsigned (&d)[2], const unsigned (&a)[4],
                                         unsigned b0, unsigned b1) {
    asm volatile(
        "mma.sync.aligned.m16n8k32.row.col.f16.e4m3.e4m3.f16 "
        "{%0,%1}, {%2,%3,%4,%5}, {%6,%7}, {%0,%1};"
        : "+r"(d[0]), "+r"(d[1])
        : "r"(a[0]), "r"(a[1]), "r"(a[2]), "r"(a[3]), "r"(b0), "r"(b1));
}
__device__ __forceinline__ void bar_group(int g) {
    asm volatile("bar.sync %0, 128;" :: "r"(g + 1) : "memory");
}

// B tile: 128 N-rows x 256B = 32KB. 128 threads x 16 cp16.
__device__ __forceinline__ void load_B(unsigned sb, const unsigned char* Bp,
                                       int j, int gtid) {
#pragma unroll
    for (int it = 0; it < 16; it++) {
        int idx = gtid + it * 128;
        int r = idx >> 4, c = idx & 15;
        cp16(sb + SWZ8(r, c), Bp + (j * 128 + r) * DIM + c * 16);
    }
    cp_commit();
}

__global__ void __launch_bounds__(256, 1) simreduce_kernel() {
    extern __shared__ __align__(128) char smem[];
    const unsigned sbase = (unsigned)__cvta_generic_to_shared(smem);
    const unsigned sA = sbase + SMEM_A;

    const int tid = threadIdx.x;
    const int bid = blockIdx.x;
    const int wid = tid >> 5;
    const int lane = tid & 31;
    const int group = wid >> 2;      // 0: warps 0-3, 1: warps 4-7
    const int gtid = tid & 127;
    const int wig = wid & 3;         // warp-in-group
    const int mhalf = wig & 1;       // 64 M-rows
    const int nhalf = wig >> 1;      // 64 N-cols

    const unsigned sBg[2] = {sbase + SMEM_B(group, 0), sbase + SMEM_B(group, 1)};

    // ---- work decode: matrix + global tile range [g0, g1) over 128-col tiles ----
    int matrix, g0, g1;
    if (bid < 74) {
        matrix = 0;
        g0 = (1024 * bid) / 74;
        g1 = (1024 * (bid + 1)) / 74;
    } else if (bid < 111) {
        int c = bid - 74;
        matrix = 1;
        g0 = (528 * c) / 37;
        g1 = (528 * (c + 1)) / 37;
    } else {
        int c = bid - 111;
        matrix = 2;
        g0 = (528 * c) / 37;
        g1 = (528 * (c + 1)) / 37;
    }

    const unsigned char* Aptr = (matrix == 2) ? g_z2 : g_z1;
    const unsigned char* Bptr = (matrix == 1) ? g_z1 : g_z2;
    const int rowTarget = (matrix == 0) ? 0 : (1 + matrix);
    const int colTarget = (matrix == 0) ? 1 : (1 + matrix);
    const bool symmetric = (matrix != 0);

    const int lrow = lane & 7, quad = lane >> 3;
    int aRow[4];
#pragma unroll
    for (int mi = 0; mi < 4; mi++)
        aRow[mi] = mhalf * 64 + mi * 16 + lrow + (quad & 1) * 8;
    const int aCq = quad >> 1;
    int bRow[4];
#pragma unroll
    for (int pq = 0; pq < 4; pq++)
        bRow[pq] = nhalf * 64 + pq * 16 + lrow + (quad >> 1) * 8;
    const int bCq = quad & 1;

    const int erow = lane >> 2;        // accumulator row within fragment
    const int ecol = (lane & 3) * 2;   // accumulator col within n8

    int g = g0;
    while (g < g1) {
        // ---- segment decode: stripe + local tile range [j0, j0+len) ----
        int stripe, j0, len;
        if (matrix == 0) {
            stripe = g >> 5;
            j0 = g & 31;
            len = min(g1 - g, 32 - j0);
        } else {
            int P = g / 33, o = g % 33;
            int run1 = 32 - P;           // stripe P: tiles j = P..31
            if (o < run1) {
                stripe = P; j0 = P + o;
                len = min(g1 - g, run1 - o);
            } else {                      // stripe 31-P: tiles j = 31-P..31
                stripe = 31 - P;
                int oo = o - run1;
                j0 = (31 - P) + oo;
                len = min(g1 - g, 33 - o);
            }
        }
        const int row0 = stripe * 128;
        const int ntg = (len > group) ? ((len - group + 1) >> 1) : 0;

        __syncthreads();   // both groups done with previous segment's smem

        // ---- prologue: B(t0) + A; wait all; CTA sync ----
        if (ntg > 0) load_B(sBg[0], Bptr, j0 + group, gtid);
#pragma unroll
        for (int it = 0; it < 8; it++) {
            int idx = tid + it * 256;
            int r = idx >> 4, c = idx & 15;
            cp16(sA + SWZ8(r, c), Aptr + (row0 + r) * DIM + c * 16);
        }
        cp_commit();
        cp_wait<0>();
        __syncthreads();     // A + own-group B(t0) visible everywhere

        float part[8];
#pragma unroll
        for (int k = 0; k < 8; k++) part[k] = 0.f;

        for (int t = 0; t < ntg; t++) {
            const int j = j0 + group + 2 * t;
            const unsigned sBj = sBg[t & 1];

            if (t > 0) {
                cp_wait<0>();        // B(t) landed (own)
                bar_group(group);    // ...group-wide; also certifies MMA(t-1)
                                     // reads of buf[(t+1)&1] are done
            }
            // refill buf[(t+1)&1] with tile t+1 (safe: last read was t-1)
            if (t + 1 < ntg) load_B(sBg[(t + 1) & 1], Bptr, j + 2, gtid);

            unsigned acc[4][8][2];
#pragma unroll
            for (int mi = 0; mi < 4; mi++)
#pragma unroll
                for (int ni = 0; ni < 8; ni++) {
                    acc[mi][ni][0] = 0u;
                    acc[mi][ni][1] = 0u;
                }

#pragma unroll
            for (int ks = 0; ks < 8; ks++) {       // K=32 per step
                unsigned a[4][4];
#pragma unroll
                for (int mi = 0; mi < 4; mi++) {
                    unsigned addr = sA + (aRow[mi] << 8) +
                                    ((((2 * ks + aCq) ^ (aRow[mi] & 7)) & 15) << 4);
                    ldsm4(a[mi], addr);
                }
                unsigned b[4][4];
#pragma unroll
                for (int pq = 0; pq < 4; pq++) {
                    unsigned addr = sBj + (bRow[pq] << 8) +
                                    ((((2 * ks + bCq) ^ (bRow[pq] & 7)) & 15) << 4);
                    ldsm4(b[pq], addr);
                }
#pragma unroll
                for (int mi = 0; mi < 4; mi++)
#pragma unroll
                    for (int ni = 0; ni < 8; ni++)
                        mma_fp8h(acc[mi][ni], a[mi],
                                 b[ni >> 1][(ni & 1) * 2],
                                 b[ni >> 1][(ni & 1) * 2 + 1]);
            }

            // ---- epilogue: 2^acc via ex2.f16x2, diag zeroing, fp16x2 sums ----
            const bool maybeDiag = (j == stripe);
            const bool doCol = (!symmetric) || !maybeDiag;

            unsigned colh[8];
#pragma unroll
            for (int ni = 0; ni < 8; ni++) colh[ni] = 0u;

#pragma unroll
            for (int mi = 0; mi < 4; mi++) {
                unsigned E0 = 0u, E1 = 0u;
                int rr0 = row0 + mhalf * 64 + mi * 16 + erow;   // global rows
                int rr1 = rr0 + 8;
#pragma unroll
                for (int ni = 0; ni < 8; ni++) {
                    unsigned e01 = ex2h2(acc[mi][ni][0]);   // row rr0, cols cc0,cc0+1
                    unsigned e23 = ex2h2(acc[mi][ni][1]);   // row rr1
                    if (maybeDiag) {
                        int cc0 = j * 128 + nhalf * 64 + ni * 8 + ecol;
                        int cc1 = cc0 + 1;
                        if (rr0 == cc0) e01 &= 0xFFFF0000u;  // zero diagonal (exact)
                        if (rr0 == cc1) e01 &= 0x0000FFFFu;
                        if (rr1 == cc0) e23 &= 0xFFFF0000u;
                        if (rr1 == cc1) e23 &= 0x0000FFFFu;
                    }
                    E0 = hadd2u(E0, e01);
                    E1 = hadd2u(E1, e23);
                    colh[ni] = hadd2u(colh[ni], hadd2u(e01, e23));
                }
                float2 f0 = __half22float2(*(__half2*)&E0);
                float2 f1 = __half22float2(*(__half2*)&E1);
                part[mi * 2 + 0] += f0.x + f0.y;
                part[mi * 2 + 1] += f1.x + f1.y;
            }

            // column partials: fp16x2 xor-shfl over the 8 erow groups, then REDG
            if (doCol) {
                float* ctgt = &g_rowsum[colTarget][j * 128 + nhalf * 64];
#pragma unroll
                for (int ni = 0; ni < 8; ni++) {
                    unsigned v = colh[ni];
                    v = hadd2u(v, __shfl_xor_sync(0xffffffffu, v, 4));
                    v = hadd2u(v, __shfl_xor_sync(0xffffffffu, v, 8));
                    v = hadd2u(v, __shfl_xor_sync(0xffffffffu, v, 16));
                    if (lane < 4) {
                        float2 f = __half22float2(*(__half2*)&v);
                        int col = ni * 8 + lane * 2;
                        atomicAdd(ctgt + col,     f.x);
                        atomicAdd(ctgt + col + 1, f.y);
                    }
                }
            }
        }

        // flush register row partials for this segment's stripe
#pragma unroll
        for (int k = 0; k < 8; k++) {
            part[k] += __shfl_xor_sync(0xffffffffu, part[k], 1);
            part[k] += __shfl_xor_sync(0xffffffffu, part[k], 2);
        }
        if ((lane & 3) == 0) {
#pragma unroll
            for (int mi = 0; mi < 4; mi++) {
                int r = row0 + mhalf * 64 + mi * 16 + erow;
                atomicAdd(&g_rowsum[rowTarget][r],     part[mi * 2 + 0]);
                atomicAdd(&g_rowsum[rowTarget][r + 8], part[mi * 2 + 1]);
            }
        }

        g += len;
    }
}

// ---------------------------------------------------------------------------
// Kernel 3: final losses. Diag is precomputed (exact fp32) in g_diag.
// row i    : log(rowsum12[i] + rowsum11m[i] + e^{10 d}) - 10 d
// row N+i  : log(rowsum22m[i] + colsum12[i] + e^{10 d}) - 10 d
// ---------------------------------------------------------------------------
__global__ void loss_kernel(float* __restrict__ out) {
    int i = blockIdx.x * blockDim.x + threadIdx.x;
    if (i < NROWS) {
        float d = g_diag[i];
        float ed = fast_ex2(d * EXPSC);
        float dl = d * 10.0f;
        out[i]         = logf(g_rowsum[0][i] + g_rowsum[2][i] + ed) - dl;
        out[NROWS + i] = logf(g_rowsum[3][i] + g_rowsum[1][i] + ed) - dl;
    }
}

extern "C" void kernel_launch(void* const* d_in, const int* in_sizes, int n_in,
                              void* d_out, int out_size) {
    const float* x1 = (const float*)d_in[0];
    const float* x2 = (const float*)d_in[1];

    normalize_kernel<<<512, 256>>>(x1, x2);

    cudaFuncSetAttribute(simreduce_kernel,
                         cudaFuncAttributeMaxDynamicSharedMemorySize, SMEM_TOTAL);
    simreduce_kernel<<<148, 256, SMEM_TOTAL>>>();

    loss_kernel<<<16, 256>>>((float*)d_out);
}

// round 16
// speedup vs baseline: 1.0652x; 1.0652x over previous
#include <cuda_runtime.h>
#include <cuda_fp16.h>

#define NROWS 4096
#define DIM 256
#define EXPSC 14.4269504088896340736f  /* 10 * log2(e) */
#define SQRT_EXPSC 3.7982825381f       /* sqrt(EXPSC) */

// persistent device scratch (no allocations allowed)
// z vectors are L2-normalized AND scaled by SQRT_EXPSC: dot of two stored
// vectors = EXPSC * cosine_sim (exp2-ready).
__device__ __half g_z1[NROWS * DIM];
__device__ __half g_z2[NROWS * DIM];
// 0: rowsum(exp sim12, diag zeroed), 1: colsum(exp sim12, diag zeroed),
// 2: rowsum(exp sim11 masked), 3: rowsum(exp sim22 masked)
__device__ float g_rowsum[4][NROWS];
__device__ float g_diag[NROWS];        // exact fp32 cosine(x1_i, x2_i)

__device__ __forceinline__ float fast_ex2(float x) {
    float y;
    asm("ex2.approx.f32 %0, %1;" : "=f"(y) : "f"(x));
    return y;
}
__device__ __forceinline__ unsigned ex2h2(unsigned x) {
    unsigned y;
    asm("ex2.approx.f16x2 %0, %1;" : "=r"(y) : "r"(x));
    return y;
}
__device__ __forceinline__ unsigned hadd2u(unsigned a, unsigned b) {
    unsigned d;
    asm("add.rn.f16x2 %0, %1, %2;" : "=r"(d) : "r"(a), "r"(b));
    return d;
}

// ---------------------------------------------------------------------------
// Kernel 1: per row i: norms, exact fp32 cross dot -> g_diag, normalize *
// SQRT_EXPSC -> fp16 z1/z2. Zeroes g_rowsum. One warp per row pair.
// ---------------------------------------------------------------------------
__global__ void normalize_kernel(const float* __restrict__ x1,
                                 const float* __restrict__ x2) {
    int gt = blockIdx.x * blockDim.x + threadIdx.x;
    if (gt < 4 * NROWS) (&g_rowsum[0][0])[gt] = 0.0f;

    int w = gt >> 5;
    int lane = threadIdx.x & 31;

    const float4* p1 = (const float4*)(x1 + w * DIM);
    const float4* p2 = (const float4*)(x2 + w * DIM);
    float4 a0 = p1[lane], a1 = p1[lane + 32];
    float4 b0 = p2[lane], b1 = p2[lane + 32];

    float s1 = a0.x*a0.x + a0.y*a0.y + a0.z*a0.z + a0.w*a0.w
             + a1.x*a1.x + a1.y*a1.y + a1.z*a1.z + a1.w*a1.w;
    float s2 = b0.x*b0.x + b0.y*b0.y + b0.z*b0.z + b0.w*b0.w
             + b1.x*b1.x + b1.y*b1.y + b1.z*b1.z + b1.w*b1.w;
    float dd = a0.x*b0.x + a0.y*b0.y + a0.z*b0.z + a0.w*b0.w
             + a1.x*b1.x + a1.y*b1.y + a1.z*b1.z + a1.w*b1.w;
#pragma unroll
    for (int o = 16; o; o >>= 1) {
        s1 += __shfl_xor_sync(0xffffffffu, s1, o);
        s2 += __shfl_xor_sync(0xffffffffu, s2, o);
        dd += __shfl_xor_sync(0xffffffffu, dd, o);
    }
    float n1 = fmaxf(sqrtf(s1), 1e-8f);
    float n2 = fmaxf(sqrtf(s2), 1e-8f);
    float sc1 = SQRT_EXPSC / n1;
    float sc2 = SQRT_EXPSC / n2;

    __half2 h0 = __floats2half2_rn(a0.x * sc1, a0.y * sc1);
    __half2 h1 = __floats2half2_rn(a0.z * sc1, a0.w * sc1);
    __half2 h2 = __floats2half2_rn(a1.x * sc1, a1.y * sc1);
    __half2 h3 = __floats2half2_rn(a1.z * sc1, a1.w * sc1);
    uint2 u0 = make_uint2(*(unsigned*)&h0, *(unsigned*)&h1);
    uint2 u1 = make_uint2(*(unsigned*)&h2, *(unsigned*)&h3);
    *(uint2*)(g_z1 + w * DIM + lane * 4) = u0;
    *(uint2*)(g_z1 + w * DIM + 128 + lane * 4) = u1;

    h0 = __floats2half2_rn(b0.x * sc2, b0.y * sc2);
    h1 = __floats2half2_rn(b0.z * sc2, b0.w * sc2);
    h2 = __floats2half2_rn(b1.x * sc2, b1.y * sc2);
    h3 = __floats2half2_rn(b1.z * sc2, b1.w * sc2);
    u0 = make_uint2(*(unsigned*)&h0, *(unsigned*)&h1);
    u1 = make_uint2(*(unsigned*)&h2, *(unsigned*)&h3);
    *(uint2*)(g_z2 + w * DIM + lane * 4) = u0;
    *(uint2*)(g_z2 + w * DIM + 128 + lane * 4) = u1;

    if (lane == 0) g_diag[w] = dd / (n1 * n2);
}

// ---------------------------------------------------------------------------
// Kernel 2: fused tile-GEMM + exp row/col-reduce. 148 CTAs, 384 threads =
// THREE warp-groups (one warp of each group per SMSP -> tensor pipe stays
// fed through the other groups' ldsm/epilogue phases). fp16 in/accumulate.
// Group tile = 128 rows x 64 cols x K=256 (warp tile 64x32); groups take
// local tiles jj % 3 == group. B staged in 16KB K-half chunks, buffer
// parity = K-half, double-buffered per group, ONE group barrier per stage.
// MMA outputs are EXPSC*sim; epilogue = ex2.f16x2 + fp16x2 reductions.
//   CTA 0..73   : sim12 (z1 x z2^T), 2048 tiles.  row->rs[0], col->rs[1].
//   CTA 74..110 : sim11 upper-tri (1056 tiles, pair-ordered stripes).
//   CTA 111..147: sim22 upper-tri.   row->target; col->target by symmetry
//                 (diagonal-block tiles: rowsum only — full block computed).
// ---------------------------------------------------------------------------
#define SWZA(r, c) (((r) << 9) | ((((c) ^ ((r) & 7))) << 4))          /* A: 512B rows */
#define SWZB(r, c) (((r) << 8) | ((((c) ^ ((r) & 7)) & 15) << 4))     /* B: 256B rows */
#define SMEM_A 0
#define SMEM_B(grp, buf) (65536 + ((grp) * 2 + (buf)) * 16384)
#define SMEM_TOTAL 163840

__device__ __forceinline__ void cp16(unsigned d, const void* s) {
    asm volatile("cp.async.cg.shared.global [%0], [%1], 16;" :: "r"(d), "l"(s));
}
__device__ __forceinline__ void cp_commit() {
    asm volatile("cp.async.commit_group;");
}
template <int n>
__device__ __forceinline__ void cp_wait() {
    asm volatile("cp.async.wait_group %0;" :: "n"(n));
}
__device__ __forceinline__ void ldsm4(unsigned (&r)[4], unsigned addr) {
    asm volatile("ldmatrix.sync.aligned.m8n8.x4.shared.b16 {%0,%1,%2,%3}, [%4];"
                 : "=r"(r[0]), "=r"(r[1]), "=r"(r[2]), "=r"(r[3]) : "r"(addr));
}
__device__ __forceinline__ void mma16816h(unsigned (&d)[2], const unsigned (&a)[4],
                                          unsigned b0, unsigned b1) {
    asm volatile(
        "mma.sync.aligned.m16n8k16.row.col.f16.f16.f16.f16 "
        "{%0,%1}, {%2,%3,%4,%5}, {%6,%7}, {%0,%1};"
        : "+r"(d[0]), "+r"(d[1])
        : "r"(a[0]), "r"(a[1]), "r"(a[2]), "r"(a[3]), "r"(b0), "r"(b1));
}
__device__ __forceinline__ void bar_group(int g) {
    asm volatile("bar.sync %0, 128;" :: "r"(g + 1) : "memory");
}

// B chunk: 64 N-rows x 128 K fp16 = 16KB. 128 threads x 8 cp16.
__device__ __forceinline__ void load_chunk(unsigned sb, const __half* Bp,
                                           int j, int khalf, int gtid) {
#pragma unroll
    for (int it = 0; it < 8; it++) {
        int idx = gtid + it * 128;
        int r = idx >> 4, c = idx & 15;
        cp16(sb + SWZB(r, c), Bp + (j * 64 + r) * DIM + khalf * 128 + c * 8);
    }
    cp_commit();
}

__global__ void __launch_bounds__(384, 1) simreduce_kernel() {
    extern __shared__ __align__(128) char smem[];
    const unsigned sbase = (unsigned)__cvta_generic_to_shared(smem);
    const unsigned sA = sbase + SMEM_A;

    const int tid = threadIdx.x;
    const int bid = blockIdx.x;
    const int wid = tid >> 5;
    const int lane = tid & 31;
    const int group = wid >> 2;      // 0,1,2 (warps 0-3 / 4-7 / 8-11)
    const int gtid = tid & 127;
    const int wig = wid & 3;         // warp-in-group = SMSP id
    const int mhalf = wig & 1;       // 64 M-rows
    const int nhalf = wig >> 1;      // 32 N-cols

    const unsigned sB0 = sbase + SMEM_B(group, 0);
    const unsigned sB1 = sbase + SMEM_B(group, 1);

    // ---- work decode: matrix + global tile range [g0, g1) over 64-col tiles ----
    int matrix, g0, g1;
    if (bid < 74) {
        matrix = 0;
        g0 = (2048 * bid) / 74;
        g1 = (2048 * (bid + 1)) / 74;
    } else if (bid < 111) {
        int c = bid - 74;
        matrix = 1;
        g0 = (1056 * c) / 37;
        g1 = (1056 * (c + 1)) / 37;
    } else {
        int c = bid - 111;
        matrix = 2;
        g0 = (1056 * c) / 37;
        g1 = (1056 * (c + 1)) / 37;
    }

    const __half* Aptr = (matrix == 2) ? g_z2 : g_z1;
    const __half* Bptr = (matrix == 1) ? g_z1 : g_z2;
    const int rowTarget = (matrix == 0) ? 0 : (1 + matrix);
    const int colTarget = (matrix == 0) ? 1 : (1 + matrix);
    const bool symmetric = (matrix != 0);

    const int lrow = lane & 7, quad = lane >> 3;
    int aRow[4];
#pragma unroll
    for (int mi = 0; mi < 4; mi++)
        aRow[mi] = mhalf * 64 + mi * 16 + lrow + (quad & 1) * 8;
    const int aCq = quad >> 1;
    int bRow[2];
#pragma unroll
    for (int pq = 0; pq < 2; pq++)
        bRow[pq] = nhalf * 32 + pq * 16 + lrow + (quad >> 1) * 8;
    const int bCq = quad & 1;

    const int erow = lane >> 2;        // accumulator row within fragment
    const int ecol = (lane & 3) * 2;   // accumulator col within n8

    int g = g0;
    while (g < g1) {
        // ---- segment decode: stripe + local tile range [j0, j0+len) (64-col) ----
        int stripe, j0, len;
        if (matrix == 0) {
            stripe = g >> 6;
            j0 = g & 63;
            len = min(g1 - g, 64 - j0);
        } else {
            int P = g / 66, o = g % 66;
            int run1 = 64 - 2 * P;       // stripe P: tiles j = 2P..63
            if (o < run1) {
                stripe = P; j0 = 2 * P + o;
                len = min(g1 - g, run1 - o);
            } else {                      // stripe 31-P: tiles j = 2(31-P)..63
                stripe = 31 - P;
                int oo = o - run1;
                j0 = 2 * (31 - P) + oo;
                len = min(g1 - g, 66 - o);
            }
        }
        const int row0 = stripe * 128;
        const int ntg = (len > group) ? ((len - group + 2) / 3) : 0;
        const int jg0 = j0 + group;

        __syncthreads();   // all groups done with previous segment's smem

        // ---- prologue: B(t0,k0), A, B(t0,k1) ----
        if (ntg > 0) load_chunk(sB0, Bptr, jg0, 0, gtid);
        else         cp_commit();                                  // c1
#pragma unroll
        for (int it = 0; it < 11; it++) {
            int idx = tid + it * 384;
            if (idx < 4096) {
                int r = idx >> 5, c = idx & 31;
                cp16(sA + SWZA(r, c), Aptr + (row0 + r) * DIM + c * 8);
            }
        }
        cp_commit();                                               // c2 (A)
        if (ntg > 0) load_chunk(sB1, Bptr, jg0, 1, gtid);
        else         cp_commit();                                  // c3
        cp_wait<1>();        // c1 + c2 done (c3 pending)
        __syncthreads();     // A + buf0 visible everywhere

        float part[8];
#pragma unroll
        for (int k = 0; k < 8; k++) part[k] = 0.f;

        for (int t = 0; t < ntg; t++) {
            const int j = jg0 + 3 * t;

            unsigned acc[4][4][2];
#pragma unroll
            for (int mi = 0; mi < 4; mi++)
#pragma unroll
                for (int ni = 0; ni < 4; ni++) {
                    acc[mi][ni][0] = 0u;
                    acc[mi][ni][1] = 0u;
                }

            // ---- two K-half stages, one group barrier each ----
#pragma unroll
            for (int kh = 0; kh < 2; kh++) {
                const unsigned sBj = kh ? sB1 : sB0;
                if (!(t == 0 && kh == 0)) {   // first stage covered by prologue
                    cp_wait<0>();
                    bar_group(group);         // chunk visible group-wide; also
                                              // certifies reads of the buffer we
                                              // refill next are complete
                }
                if (kh == 0) { if (t >= 1)      load_chunk(sB1, Bptr, j,     1, gtid); }
                else         { if (t + 1 < ntg) load_chunk(sB0, Bptr, j + 3, 0, gtid); }

#pragma unroll
                for (int ks = 0; ks < 8; ks++) {
                    const int ksg = kh * 8 + ks;
                    unsigned a[4][4];
#pragma unroll
                    for (int mi = 0; mi < 4; mi++) {
                        unsigned addr = sA + (aRow[mi] << 9) +
                                        (((2 * ksg + aCq) ^ (aRow[mi] & 7)) << 4);
                        ldsm4(a[mi], addr);
                    }
                    unsigned b[2][4];
#pragma unroll
                    for (int pq = 0; pq < 2; pq++) {
                        unsigned addr = sBj + (bRow[pq] << 8) +
                                        ((((2 * ks + bCq) ^ (bRow[pq] & 7)) & 15) << 4);
                        ldsm4(b[pq], addr);
                    }
#pragma unroll
                    for (int mi = 0; mi < 4; mi++)
#pragma unroll
                        for (int ni = 0; ni < 4; ni++)
                            mma16816h(acc[mi][ni], a[mi],
                                      b[ni >> 1][(ni & 1) * 2],
                                      b[ni >> 1][(ni & 1) * 2 + 1]);
                }
            }

            // ---- epilogue: 2^acc via ex2.f16x2, diag zeroing, fp16x2 sums ----
            const bool maybeDiag = ((j >> 1) == stripe);
            const bool doCol = (!symmetric) || !maybeDiag;

            unsigned colh[4];
#pragma unroll
            for (int ni = 0; ni < 4; ni++) colh[ni] = 0u;

#pragma unroll
            for (int mi = 0; mi < 4; mi++) {
                unsigned E0 = 0u, E1 = 0u;
                int rr0 = row0 + mhalf * 64 + mi * 16 + erow;   // global rows
                int rr1 = rr0 + 8;
#pragma unroll
                for (int ni = 0; ni < 4; ni++) {
                    unsigned e01 = ex2h2(acc[mi][ni][0]);   // row rr0
                    unsigned e23 = ex2h2(acc[mi][ni][1]);   // row rr1
                    if (maybeDiag) {
                        int cc0 = j * 64 + nhalf * 32 + ni * 8 + ecol;
                        int cc1 = cc0 + 1;
                        if (rr0 == cc0) e01 &= 0xFFFF0000u;  // zero diagonal
                        if (rr0 == cc1) e01 &= 0x0000FFFFu;
                        if (rr1 == cc0) e23 &= 0xFFFF0000u;
                        if (rr1 == cc1) e23 &= 0x0000FFFFu;
                    }
                    E0 = hadd2u(E0, e01);
                    E1 = hadd2u(E1, e23);
                    colh[ni] = hadd2u(colh[ni], hadd2u(e01, e23));
                }
                float2 f0 = __half22float2(*(__half2*)&E0);
                float2 f1 = __half22float2(*(__half2*)&E1);
                part[mi * 2 + 0] += f0.x + f0.y;
                part[mi * 2 + 1] += f1.x + f1.y;
            }

            // column partials: fp16x2 xor-shfl over the 8 erow groups, then REDG
            if (doCol) {
                float* ctgt = &g_rowsum[colTarget][j * 64 + nhalf * 32];
#pragma unroll
                for (int ni = 0; ni < 4; ni++) {
                    unsigned v = colh[ni];
                    v = hadd2u(v, __shfl_xor_sync(0xffffffffu, v, 4));
                    v = hadd2u(v, __shfl_xor_sync(0xffffffffu, v, 8));
                    v = hadd2u(v, __shfl_xor_sync(0xffffffffu, v, 16));
                    if (lane < 4) {
                        float2 f = __half22float2(*(__half2*)&v);
                        int col = ni * 8 + lane * 2;
                        atomicAdd(ctgt + col,     f.x);
                        atomicAdd(ctgt + col + 1, f.y);
                    }
                }
            }
        }

        // flush register row partials for this segment's stripe
#pragma unroll
        for (int k = 0; k < 8; k++) {
            part[k] += __shfl_xor_sync(0xffffffffu, part[k], 1);
            part[k] += __shfl_xor_sync(0xffffffffu, part[k], 2);
        }
        if ((lane & 3) == 0) {
#pragma unroll
            for (int mi = 0; mi < 4; mi++) {
                int r = row0 + mhalf * 64 + mi * 16 + erow;
                atomicAdd(&g_rowsum[rowTarget][r],     part[mi * 2 + 0]);
                atomicAdd(&g_rowsum[rowTarget][r + 8], part[mi * 2 + 1]);
            }
        }

        g += len;
    }
}

// ---------------------------------------------------------------------------
// Kernel 3: final losses. Diag is precomputed (exact fp32) in g_diag.
// row i    : log(rowsum12[i] + rowsum11m[i] + e^{10 d}) - 10 d
// row N+i  : log(rowsum22m[i] + colsum12[i] + e^{10 d}) - 10 d
// ---------------------------------------------------------------------------
__global__ void loss_kernel(float* __restrict__ out) {
    int i = blockIdx.x * blockDim.x + threadIdx.x;
    if (i < NROWS) {
        float d = g_diag[i];
        float ed = fast_ex2(d * EXPSC);
        float dl = d * 10.0f;
        out[i]         = logf(g_rowsum[0][i] + g_rowsum[2][i] + ed) - dl;
        out[NROWS + i] = logf(g_rowsum[3][i] + g_rowsum[1][i] + ed) - dl;
    }
}

extern "C" void kernel_launch(void* const* d_in, const int* in_sizes, int n_in,
                              void* d_out, int out_size) {
    const float* x1 = (const float*)d_in[0];
    const float* x2 = (const float*)d_in[1];

    normalize_kernel<<<512, 256>>>(x1, x2);

    cudaFuncSetAttribute(simreduce_kernel,
                         cudaFuncAttributeMaxDynamicSharedMemorySize, SMEM_TOTAL);
    simreduce_kernel<<<148, 384, SMEM_TOTAL>>>();

    loss_kernel<<<16, 256>>>((float*)d_out);
}